// round 16
// baseline (speedup 1.0000x reference)
#include <cuda_runtime.h>
#include <cuda_bf16.h>
#include <cstdint>

// YOLO loss: pred [16384,7,7,30] f32, target [16384,7,7,30] f32 -> scalar f32.
// Pure HBM-bound reduction (192.6 MB in, 4 B out). 15-round exploration maps
// the chip's read-stream plateau at ~5.95 TB/s; this kernel runs within ~2%
// of that floor (prologue ramp + tail account for the rest).
//
// R16 (final): R13 verbatim — TMA 15360B chunks, 2-stage double buffer,
// 3 blocks/SM (GRID=444), exact load balance (14 chunks/block + 7168
// remainder cells absorbed in the prologue under TMA latency), deterministic
// fixed-point atomic tail (scaled int64; integer add is exactly commutative).
// Micro-tweak: remainder loads via __ldcs (streaming, no L1 pollution).

#define S 7
#define CELLS_PER_IMG 49
#define NCH 30
#define BATCH 16384
#define TOTAL_CELLS (BATCH * CELLS_PER_IMG)    // 802816
#define BLOCK_CELLS 128
#define GRID 444                               // 148 SMs * 3
#define CHUNKS_PER_BLOCK 14
#define NCHUNKS_MAIN (GRID * CHUNKS_PER_BLOCK) // 6216
#define REM_START_CELL (NCHUNKS_MAIN * BLOCK_CELLS)  // 795648
#define REM_CELLS (TOTAL_CELLS - REM_START_CELL)     // 7168
#define CHUNK_FLOATS (BLOCK_CELLS * NCH)       // 3840
#define CHUNK_BYTES (CHUNK_FLOATS * 4)         // 15360
#define STAGE_FLOATS (2 * CHUNK_FLOATS)        // pred + tgt
#define STAGE_BYTES (2 * CHUNK_BYTES)          // 30720
#define SMEM_BYTES (2 * STAGE_BYTES)           // 61440
#define STEP (1.0f / 7.0f)
#define LAMBDA_COORD 5.0f
#define LAMBDA_NOOBJ 0.5f
#define FXSCALE 2097152.0f                     // 2^21
#define FXINV (1.0f / 2097152.0f)

__device__ long long g_fxsum;      // zero-init; reset by last block each launch
__device__ unsigned int g_count;   // zero-init; reset by last block each launch

struct Box { float x1, y1, x2, y2; };

__device__ __forceinline__ Box convert_box(float x, float y, float w, float h,
                                           float gi, float gj) {
    float cx = (x + gi) * STEP;
    float cy = (y + gj) * STEP;
    Box b;
    b.x1 = fmaxf(cx - 0.5f * w, 0.0f);
    b.y1 = fmaxf(cy - 0.5f * h, 0.0f);
    b.x2 = fminf(cx + 0.5f * w, 1.0f);
    b.y2 = fminf(cy + 0.5f * h, 1.0f);
    return b;
}

__device__ __forceinline__ float iou(const Box& t, const Box& p) {
    // Faithful to reference: inter not clamped; zero if inter <= 0.
    float minx = fmaxf(t.x1, p.x1);
    float miny = fmaxf(t.y1, p.y1);
    float maxx = fminf(t.x2, p.x2);
    float maxy = fminf(t.y2, p.y2);
    float inter = (maxy - miny) * (maxx - minx);
    float uni = (p.x2 - p.x1) * (p.y2 - p.y1)
              + (t.y2 - t.y1) * (t.x2 - t.x1) - inter;
    return (inter > 0.0f) ? inter / (uni + 1e-05f) : 0.0f;
}

// Per-cell loss from 30 pred floats + 30 target floats.
__device__ __forceinline__ float cell_loss(const float* __restrict__ P,
                                           const float* __restrict__ T,
                                           int r) {
    const float gi = (float)(r / S);
    const float gj = (float)(r % S);

    const float t0 = T[0], t1 = T[1], t2 = T[2], t3 = T[3], tconf = T[4];
    Box tb = convert_box(t0, t1, t2, t3, gi, gj);
    Box pb1 = convert_box(P[0], P[1], P[2], P[3], gi, gj);
    Box pb2 = convert_box(P[5], P[6], P[7], P[8], gi, gj);
    float iou1 = iou(tb, pb1);
    float iou2 = iou(tb, pb2);

    bool sel2 = (iou1 <= iou2);
    float conf_t = sel2 ? iou2 : iou1;
    float px = sel2 ? P[5] : P[0];
    float py = sel2 ? P[6] : P[1];
    float pw = sel2 ? P[7] : P[2];
    float ph = sel2 ? P[8] : P[3];
    float pconf = sel2 ? P[9] : P[4];

    float obj = (tconf > 0.0f) ? 1.0f : 0.0f;
    float noobj = (tconf == 0.0f) ? 1.0f : 0.0f;

    float dconf = pconf - conf_t;
    float dx = px - t0, dy = py - t1, dw = pw - t2, dh = ph - t3;
    float coord = dx * dx + dy * dy + dw * dw + dh * dh;

    float cls = 0.0f;
#pragma unroll
    for (int k = 10; k < NCH; k++) {
        float d = P[k] - T[k];
        cls = fmaf(d, d, cls);
    }

    float d4 = P[4] - T[4];
    float d9 = P[9] - T[9];
    float noobj_term = d4 * d4 + d9 * d9;

    return obj * (dconf * dconf + LAMBDA_COORD * coord + cls)
         + LAMBDA_NOOBJ * noobj * noobj_term;
}

__device__ __forceinline__ uint32_t smem_u32(const void* p) {
    return (uint32_t)__cvta_generic_to_shared(p);
}

__device__ __forceinline__ void mbar_init(uint32_t mbar, uint32_t count) {
    asm volatile("mbarrier.init.shared.b64 [%0], %1;" :: "r"(mbar), "r"(count)
                 : "memory");
}

__device__ __forceinline__ void mbar_expect_tx(uint32_t mbar, uint32_t bytes) {
    asm volatile("mbarrier.arrive.expect_tx.shared.b64 _, [%0], %1;"
                 :: "r"(mbar), "r"(bytes) : "memory");
}

__device__ __forceinline__ void bulk_g2s(uint32_t sdst, const void* gsrc,
                                         uint32_t bytes, uint32_t mbar) {
    asm volatile(
        "cp.async.bulk.shared::cta.global.mbarrier::complete_tx::bytes "
        "[%0], [%1], %2, [%3];"
        :: "r"(sdst), "l"(gsrc), "r"(bytes), "r"(mbar) : "memory");
}

__device__ __forceinline__ void mbar_wait(uint32_t mbar, uint32_t parity) {
    asm volatile(
        "{\n\t"
        ".reg .pred P;\n\t"
        "WAIT_%=: \n\t"
        "mbarrier.try_wait.parity.acquire.cta.shared::cta.b64 P, [%0], %1, 0x989680;\n\t"
        "@P bra.uni DONE_%=;\n\t"
        "bra.uni WAIT_%=;\n\t"
        "DONE_%=: \n\t"
        "}"
        :: "r"(mbar), "r"(parity) : "memory");
}

__global__ void __launch_bounds__(BLOCK_CELLS)
yolo_loss_final(const float* __restrict__ pred, const float* __restrict__ tgt,
                float* __restrict__ out) {
    extern __shared__ __align__(128) float sbuf[];   // 2 stages, 61440 B
    __shared__ __align__(8) uint64_t mbar_s[2];
    __shared__ float wsum[BLOCK_CELLS / 32];

    const int tid = threadIdx.x;
    const uint32_t mbar0 = smem_u32(&mbar_s[0]);
    const uint32_t mbar1 = smem_u32(&mbar_s[1]);

    if (tid == 0) {
        mbar_init(mbar0, 1);
        mbar_init(mbar1, 1);
    }
    __syncthreads();

    // Prologue: issue TMA for iterations 0 and 1.
    if (tid == 0) {
        int c0 = blockIdx.x;
        mbar_expect_tx(mbar0, STAGE_BYTES);
        bulk_g2s(smem_u32(sbuf), pred + (size_t)c0 * CHUNK_FLOATS,
                 CHUNK_BYTES, mbar0);
        bulk_g2s(smem_u32(sbuf + CHUNK_FLOATS),
                 tgt + (size_t)c0 * CHUNK_FLOATS, CHUNK_BYTES, mbar0);
        int c1 = c0 + GRID;
        mbar_expect_tx(mbar1, STAGE_BYTES);
        bulk_g2s(smem_u32(sbuf + STAGE_FLOATS),
                 pred + (size_t)c1 * CHUNK_FLOATS, CHUNK_BYTES, mbar1);
        bulk_g2s(smem_u32(sbuf + STAGE_FLOATS + CHUNK_FLOATS),
                 tgt + (size_t)c1 * CHUNK_FLOATS, CHUNK_BYTES, mbar1);
    }

    float acc = 0.0f;

    // Remainder cells (7168), hidden under first-chunk TMA latency.
    // cell j -> block j % GRID, thread j / GRID. Streaming loads (__ldcs).
    {
        int j = blockIdx.x + GRID * tid;
        if (j < REM_CELLS) {
            const int cell = REM_START_CELL + j;
            const size_t base = (size_t)cell * NCH;   // even -> 8B aligned
            float Pr[NCH], Tr[NCH];
            const float2* p2 = reinterpret_cast<const float2*>(pred + base);
            const float2* t2 = reinterpret_cast<const float2*>(tgt + base);
#pragma unroll
            for (int k = 0; k < NCH / 2; k++) {
                float2 a = __ldcs(&p2[k]);
                float2 b = __ldcs(&t2[k]);
                Pr[2 * k] = a.x; Pr[2 * k + 1] = a.y;
                Tr[2 * k] = b.x; Tr[2 * k + 1] = b.y;
            }
            acc += cell_loss(Pr, Tr, cell % CELLS_PER_IMG);
        }
    }

    // Main pipeline: exactly 14 chunks per block.
    int ph0 = 0, ph1 = 0;
#pragma unroll 1
    for (int it = 0; it < CHUNKS_PER_BLOCK; it++) {
        const int c = blockIdx.x + it * GRID;
        const int b = it & 1;
        if (b == 0) { mbar_wait(mbar0, ph0); ph0 ^= 1; }
        else        { mbar_wait(mbar1, ph1); ph1 ^= 1; }

        const float* P = sbuf + b * STAGE_FLOATS + tid * NCH;
        const float* T = sbuf + b * STAGE_FLOATS + CHUNK_FLOATS + tid * NCH;

        const int cell = c * BLOCK_CELLS + tid;
        acc += cell_loss(P, T, cell % CELLS_PER_IMG);

        __syncthreads();   // all threads done reading buffer b

        const int nc = c + 2 * GRID;
        if (tid == 0 && nc < NCHUNKS_MAIN) {
            const uint32_t mb = b ? mbar1 : mbar0;
            mbar_expect_tx(mb, STAGE_BYTES);
            bulk_g2s(smem_u32(sbuf + b * STAGE_FLOATS),
                     pred + (size_t)nc * CHUNK_FLOATS, CHUNK_BYTES, mb);
            bulk_g2s(smem_u32(sbuf + b * STAGE_FLOATS + CHUNK_FLOATS),
                     tgt + (size_t)nc * CHUNK_FLOATS, CHUNK_BYTES, mb);
        }
    }

    // Block reduction.
#pragma unroll
    for (int off = 16; off > 0; off >>= 1)
        acc += __shfl_down_sync(0xFFFFFFFFu, acc, off);
    if ((tid & 31) == 0) wsum[tid >> 5] = acc;
    __syncthreads();

    if (tid == 0) {
        float s = wsum[0];
#pragma unroll
        for (int w = 1; w < BLOCK_CELLS / 32; w++) s += wsum[w];
        // Deterministic cross-block accumulation: scaled int64 atomic.
        // Integer addition is exactly commutative -> order-independent.
        long long fx = __float2ll_rn(s * FXSCALE);
        atomicAdd(reinterpret_cast<unsigned long long*>(&g_fxsum),
                  (unsigned long long)fx);
        __threadfence();
        unsigned int old = atomicAdd(&g_count, 1u);
        if (old == GRID - 1u) {
            // Last block: read exact integer total, write output, reset.
            long long tot = g_fxsum;
            out[0] = ((float)((double)tot * (double)FXINV)) / (float)BATCH;
            g_fxsum = 0ll;
            __threadfence();
            g_count = 0u;   // reset for next graph replay
        }
    }
}

extern "C" void kernel_launch(void* const* d_in, const int* in_sizes, int n_in,
                              void* d_out, int out_size) {
    const float* pred = (const float*)d_in[0];
    const float* tgt  = (const float*)d_in[1];
    float* out = (float*)d_out;

    cudaFuncSetAttribute(yolo_loss_final,
                         cudaFuncAttributeMaxDynamicSharedMemorySize,
                         SMEM_BYTES);
    yolo_loss_final<<<GRID, BLOCK_CELLS, SMEM_BYTES>>>(pred, tgt, out);
}

// round 17
// speedup vs baseline: 1.0073x; 1.0073x over previous
#include <cuda_runtime.h>
#include <cuda_bf16.h>
#include <cstdint>

// YOLO loss: pred [16384,7,7,30] f32, target [16384,7,7,30] f32 -> scalar f32.
// Pure HBM-bound reduction (192.6 MB in, 4 B out).
//
// FINAL (R13, best measured: 33.15us kernel, 5.95 TB/s, rel_err 0.0):
//  - TMA cp.async.bulk 15360B chunks, 2-stage double buffer, 128-thr blocks,
//    3 blocks/SM (GRID=444).
//  - Exact load balance: 14 chunks/block; the 7168 remainder cells are spread
//    across all blocks as a prologue hidden under first-chunk TMA latency.
//  - Deterministic fixed-point atomic tail: blocks atomicAdd llrint(s*2^21)
//    to an int64 (integer add is exactly commutative -> order-independent);
//    last block writes out[0] and resets state for graph replay.
// 16-round exploration: chip read-stream plateau ~5.9-5.95 TB/s regardless of
// load path/grain/depth/streams/sync topology; this sits ~2% off that floor.

#define S 7
#define CELLS_PER_IMG 49
#define NCH 30
#define BATCH 16384
#define TOTAL_CELLS (BATCH * CELLS_PER_IMG)    // 802816
#define BLOCK_CELLS 128
#define GRID 444                               // 148 SMs * 3
#define CHUNKS_PER_BLOCK 14
#define NCHUNKS_MAIN (GRID * CHUNKS_PER_BLOCK) // 6216
#define REM_START_CELL (NCHUNKS_MAIN * BLOCK_CELLS)  // 795648
#define REM_CELLS (TOTAL_CELLS - REM_START_CELL)     // 7168
#define CHUNK_FLOATS (BLOCK_CELLS * NCH)       // 3840
#define CHUNK_BYTES (CHUNK_FLOATS * 4)         // 15360
#define STAGE_FLOATS (2 * CHUNK_FLOATS)        // pred + tgt
#define STAGE_BYTES (2 * CHUNK_BYTES)          // 30720
#define SMEM_BYTES (2 * STAGE_BYTES)           // 61440
#define STEP (1.0f / 7.0f)
#define LAMBDA_COORD 5.0f
#define LAMBDA_NOOBJ 0.5f
#define FXSCALE 2097152.0f                     // 2^21
#define FXINV (1.0f / 2097152.0f)

__device__ long long g_fxsum;      // zero-init; reset by last block each launch
__device__ unsigned int g_count;   // zero-init; reset by last block each launch

struct Box { float x1, y1, x2, y2; };

__device__ __forceinline__ Box convert_box(float x, float y, float w, float h,
                                           float gi, float gj) {
    float cx = (x + gi) * STEP;
    float cy = (y + gj) * STEP;
    Box b;
    b.x1 = fmaxf(cx - 0.5f * w, 0.0f);
    b.y1 = fmaxf(cy - 0.5f * h, 0.0f);
    b.x2 = fminf(cx + 0.5f * w, 1.0f);
    b.y2 = fminf(cy + 0.5f * h, 1.0f);
    return b;
}

__device__ __forceinline__ float iou(const Box& t, const Box& p) {
    // Faithful to reference: inter not clamped; zero if inter <= 0.
    float minx = fmaxf(t.x1, p.x1);
    float miny = fmaxf(t.y1, p.y1);
    float maxx = fminf(t.x2, p.x2);
    float maxy = fminf(t.y2, p.y2);
    float inter = (maxy - miny) * (maxx - minx);
    float uni = (p.x2 - p.x1) * (p.y2 - p.y1)
              + (t.y2 - t.y1) * (t.x2 - t.x1) - inter;
    return (inter > 0.0f) ? inter / (uni + 1e-05f) : 0.0f;
}

// Per-cell loss from 30 pred floats + 30 target floats.
__device__ __forceinline__ float cell_loss(const float* __restrict__ P,
                                           const float* __restrict__ T,
                                           int r) {
    const float gi = (float)(r / S);
    const float gj = (float)(r % S);

    const float t0 = T[0], t1 = T[1], t2 = T[2], t3 = T[3], tconf = T[4];
    Box tb = convert_box(t0, t1, t2, t3, gi, gj);
    Box pb1 = convert_box(P[0], P[1], P[2], P[3], gi, gj);
    Box pb2 = convert_box(P[5], P[6], P[7], P[8], gi, gj);
    float iou1 = iou(tb, pb1);
    float iou2 = iou(tb, pb2);

    bool sel2 = (iou1 <= iou2);
    float conf_t = sel2 ? iou2 : iou1;
    float px = sel2 ? P[5] : P[0];
    float py = sel2 ? P[6] : P[1];
    float pw = sel2 ? P[7] : P[2];
    float ph = sel2 ? P[8] : P[3];
    float pconf = sel2 ? P[9] : P[4];

    float obj = (tconf > 0.0f) ? 1.0f : 0.0f;
    float noobj = (tconf == 0.0f) ? 1.0f : 0.0f;

    float dconf = pconf - conf_t;
    float dx = px - t0, dy = py - t1, dw = pw - t2, dh = ph - t3;
    float coord = dx * dx + dy * dy + dw * dw + dh * dh;

    float cls = 0.0f;
#pragma unroll
    for (int k = 10; k < NCH; k++) {
        float d = P[k] - T[k];
        cls = fmaf(d, d, cls);
    }

    float d4 = P[4] - T[4];
    float d9 = P[9] - T[9];
    float noobj_term = d4 * d4 + d9 * d9;

    return obj * (dconf * dconf + LAMBDA_COORD * coord + cls)
         + LAMBDA_NOOBJ * noobj * noobj_term;
}

__device__ __forceinline__ uint32_t smem_u32(const void* p) {
    return (uint32_t)__cvta_generic_to_shared(p);
}

__device__ __forceinline__ void mbar_init(uint32_t mbar, uint32_t count) {
    asm volatile("mbarrier.init.shared.b64 [%0], %1;" :: "r"(mbar), "r"(count)
                 : "memory");
}

__device__ __forceinline__ void mbar_expect_tx(uint32_t mbar, uint32_t bytes) {
    asm volatile("mbarrier.arrive.expect_tx.shared.b64 _, [%0], %1;"
                 :: "r"(mbar), "r"(bytes) : "memory");
}

__device__ __forceinline__ void bulk_g2s(uint32_t sdst, const void* gsrc,
                                         uint32_t bytes, uint32_t mbar) {
    asm volatile(
        "cp.async.bulk.shared::cta.global.mbarrier::complete_tx::bytes "
        "[%0], [%1], %2, [%3];"
        :: "r"(sdst), "l"(gsrc), "r"(bytes), "r"(mbar) : "memory");
}

__device__ __forceinline__ void mbar_wait(uint32_t mbar, uint32_t parity) {
    asm volatile(
        "{\n\t"
        ".reg .pred P;\n\t"
        "WAIT_%=: \n\t"
        "mbarrier.try_wait.parity.acquire.cta.shared::cta.b64 P, [%0], %1, 0x989680;\n\t"
        "@P bra.uni DONE_%=;\n\t"
        "bra.uni WAIT_%=;\n\t"
        "DONE_%=: \n\t"
        "}"
        :: "r"(mbar), "r"(parity) : "memory");
}

__global__ void __launch_bounds__(BLOCK_CELLS)
yolo_loss_final(const float* __restrict__ pred, const float* __restrict__ tgt,
                float* __restrict__ out) {
    extern __shared__ __align__(128) float sbuf[];   // 2 stages, 61440 B
    __shared__ __align__(8) uint64_t mbar_s[2];
    __shared__ float wsum[BLOCK_CELLS / 32];

    const int tid = threadIdx.x;
    const uint32_t mbar0 = smem_u32(&mbar_s[0]);
    const uint32_t mbar1 = smem_u32(&mbar_s[1]);

    if (tid == 0) {
        mbar_init(mbar0, 1);
        mbar_init(mbar1, 1);
    }
    __syncthreads();

    // Prologue: issue TMA for iterations 0 and 1.
    if (tid == 0) {
        int c0 = blockIdx.x;
        mbar_expect_tx(mbar0, STAGE_BYTES);
        bulk_g2s(smem_u32(sbuf), pred + (size_t)c0 * CHUNK_FLOATS,
                 CHUNK_BYTES, mbar0);
        bulk_g2s(smem_u32(sbuf + CHUNK_FLOATS),
                 tgt + (size_t)c0 * CHUNK_FLOATS, CHUNK_BYTES, mbar0);
        int c1 = c0 + GRID;
        mbar_expect_tx(mbar1, STAGE_BYTES);
        bulk_g2s(smem_u32(sbuf + STAGE_FLOATS),
                 pred + (size_t)c1 * CHUNK_FLOATS, CHUNK_BYTES, mbar1);
        bulk_g2s(smem_u32(sbuf + STAGE_FLOATS + CHUNK_FLOATS),
                 tgt + (size_t)c1 * CHUNK_FLOATS, CHUNK_BYTES, mbar1);
    }

    float acc = 0.0f;

    // Remainder cells (7168), hidden under first-chunk TMA latency.
    // cell j -> block j % GRID, thread j / GRID.
    {
        int j = blockIdx.x + GRID * tid;
        if (j < REM_CELLS) {
            const int cell = REM_START_CELL + j;
            const size_t base = (size_t)cell * NCH;   // even -> 8B aligned
            float Pr[NCH], Tr[NCH];
            const float2* p2 = reinterpret_cast<const float2*>(pred + base);
            const float2* t2 = reinterpret_cast<const float2*>(tgt + base);
#pragma unroll
            for (int k = 0; k < NCH / 2; k++) {
                float2 a = __ldg(&p2[k]);
                float2 b = __ldg(&t2[k]);
                Pr[2 * k] = a.x; Pr[2 * k + 1] = a.y;
                Tr[2 * k] = b.x; Tr[2 * k + 1] = b.y;
            }
            acc += cell_loss(Pr, Tr, cell % CELLS_PER_IMG);
        }
    }

    // Main pipeline: exactly 14 chunks per block.
    int ph0 = 0, ph1 = 0;
#pragma unroll 1
    for (int it = 0; it < CHUNKS_PER_BLOCK; it++) {
        const int c = blockIdx.x + it * GRID;
        const int b = it & 1;
        if (b == 0) { mbar_wait(mbar0, ph0); ph0 ^= 1; }
        else        { mbar_wait(mbar1, ph1); ph1 ^= 1; }

        const float* P = sbuf + b * STAGE_FLOATS + tid * NCH;
        const float* T = sbuf + b * STAGE_FLOATS + CHUNK_FLOATS + tid * NCH;

        const int cell = c * BLOCK_CELLS + tid;
        acc += cell_loss(P, T, cell % CELLS_PER_IMG);

        __syncthreads();   // all threads done reading buffer b

        const int nc = c + 2 * GRID;
        if (tid == 0 && nc < NCHUNKS_MAIN) {
            const uint32_t mb = b ? mbar1 : mbar0;
            mbar_expect_tx(mb, STAGE_BYTES);
            bulk_g2s(smem_u32(sbuf + b * STAGE_FLOATS),
                     pred + (size_t)nc * CHUNK_FLOATS, CHUNK_BYTES, mb);
            bulk_g2s(smem_u32(sbuf + b * STAGE_FLOATS + CHUNK_FLOATS),
                     tgt + (size_t)nc * CHUNK_FLOATS, CHUNK_BYTES, mb);
        }
    }

    // Block reduction.
#pragma unroll
    for (int off = 16; off > 0; off >>= 1)
        acc += __shfl_down_sync(0xFFFFFFFFu, acc, off);
    if ((tid & 31) == 0) wsum[tid >> 5] = acc;
    __syncthreads();

    if (tid == 0) {
        float s = wsum[0];
#pragma unroll
        for (int w = 1; w < BLOCK_CELLS / 32; w++) s += wsum[w];
        // Deterministic cross-block accumulation: scaled int64 atomic.
        // Integer addition is exactly commutative -> order-independent.
        long long fx = __float2ll_rn(s * FXSCALE);
        atomicAdd(reinterpret_cast<unsigned long long*>(&g_fxsum),
                  (unsigned long long)fx);
        __threadfence();
        unsigned int old = atomicAdd(&g_count, 1u);
        if (old == GRID - 1u) {
            // Last block: read exact integer total, write output, reset.
            long long tot = g_fxsum;
            out[0] = ((float)((double)tot * (double)FXINV)) / (float)BATCH;
            g_fxsum = 0ll;
            __threadfence();
            g_count = 0u;   // reset for next graph replay
        }
    }
}

extern "C" void kernel_launch(void* const* d_in, const int* in_sizes, int n_in,
                              void* d_out, int out_size) {
    const float* pred = (const float*)d_in[0];
    const float* tgt  = (const float*)d_in[1];
    float* out = (float*)d_out;

    cudaFuncSetAttribute(yolo_loss_final,
                         cudaFuncAttributeMaxDynamicSharedMemorySize,
                         SMEM_BYTES);
    yolo_loss_final<<<GRID, BLOCK_CELLS, SMEM_BYTES>>>(pred, tgt, out);
}